// round 1
// baseline (speedup 1.0000x reference)
#include <cuda_runtime.h>
#include <cuda_bf16.h>
#include <math.h>

// Problem constants
#define BB 4
#define SS 1024
#define KK 32
#define VV 32000
#define ROWS (BB * SS)        // 4096
#define THREADS 256
#define FULL 0xFFFFFFFFu

__global__ __launch_bounds__(THREADS)
void robust_combiner_kernel(
    const int*   __restrict__ tgt_index,            // [ROWS, 32]
    const float* __restrict__ knn_dists,            // [ROWS, 32]
    const float* __restrict__ knn_key_feature,      // [ROWS, 32]
    const float* __restrict__ network_select_probs, // [ROWS, 32]
    const float* __restrict__ fc1_w1,               // [2,4]
    const float* __restrict__ fc1_b1,               // [4]
    const float* __restrict__ fc1_w2,               // [4,1]
    const float* __restrict__ fc1_b2,               // [1]
    const float* __restrict__ fc2_w1,               // [64,32]
    const float* __restrict__ fc2_b1,               // [32]
    const float* __restrict__ fc2_w2,               // [32,2]
    const float* __restrict__ fc2_b2,               // [2]
    float*       __restrict__ out)                  // [ROWS, 32000]
{
    __shared__ float sm_d[KK];
    __shared__ float sm_lc[KK];
    __shared__ float sm_prob[KK];
    __shared__ int   sm_idx[KK];

    const int row  = blockIdx.x;
    const int tid  = threadIdx.x;
    const int lane = tid & 31;

    if (tid < 32) {
        const int base = row * KK + lane;
        const int   t  = tgt_index[base];
        const float d  = knn_dists[base];
        const float kf = knn_key_feature[base];
        const float sp = network_select_probs[base];
        const float lkf = logf(kf);
        const float lsp = logf(sp);

        // ---- label_counts: distinct nonzero labels in prefix [0..lane] ----
        // first-occurrence flag per position, then inclusive warp prefix sum
        int dup = 0;
        #pragma unroll
        for (int m = 0; m < KK; m++) {
            int tm = __shfl_sync(FULL, t, m);
            if (m < lane && tm == t) dup = 1;
        }
        int fo = (t != 0 && !dup) ? 1 : 0;
        int c = fo;
        #pragma unroll
        for (int off = 1; off < 32; off <<= 1) {
            int v = __shfl_up_sync(FULL, c, off);
            if (lane >= off) c += v;
        }
        const float lc = (float)c;

        sm_d[lane]  = d;
        sm_lc[lane] = lc;
        __syncwarp();

        // ---- noise_logit: Linear(2,4) -> tanh -> Linear(4,1) ----
        float noise = fc1_b2[0];
        #pragma unroll
        for (int j = 0; j < 4; j++) {
            float h = tanhf(lkf * fc1_w1[j] + lsp * fc1_w1[4 + j] + fc1_b1[j]);
            noise += h * fc1_w2[j];
        }

        // ---- fc2: Linear(64,32)->tanh->Linear(32,2); lane = hidden unit ----
        float acc = fc2_b1[lane];
        #pragma unroll
        for (int m = 0; m < KK; m++)
            acc += sm_d[m] * fc2_w1[m * 32 + lane];
        #pragma unroll
        for (int m = 0; m < KK; m++)
            acc += sm_lc[m] * fc2_w1[(KK + m) * 32 + lane];
        float h = tanhf(acc);

        // lambda_logit[1] = sum_j h_j * fc2_w2[j*2+1] + fc2_b2[1]
        float part = h * fc2_w2[lane * 2 + 1];
        #pragma unroll
        for (int off = 16; off >= 1; off >>= 1)
            part += __shfl_xor_sync(FULL, part, off);
        const float ll1 = part + fc2_b2[1];
        const float tempe = 1.0f / (1.0f + expf(-ll1));

        // ---- probs = softmax(-d * tempe + noise) over K ----
        float logit = -d * tempe + noise;
        float mx = logit;
        #pragma unroll
        for (int off = 16; off >= 1; off >>= 1)
            mx = fmaxf(mx, __shfl_xor_sync(FULL, mx, off));
        float e = expf(logit - mx);
        float s = e;
        #pragma unroll
        for (int off = 16; off >= 1; off >>= 1)
            s += __shfl_xor_sync(FULL, s, off);

        sm_prob[lane] = e / s;
        sm_idx[lane]  = t;
    }

    __syncthreads();

    // ---- zero this row of the output (32000 f32 = 8000 float4) ----
    float4* orow = reinterpret_cast<float4*>(out + (size_t)row * VV);
    const float4 z4 = make_float4(0.f, 0.f, 0.f, 0.f);
    #pragma unroll 4
    for (int i = tid; i < VV / 4; i += THREADS)
        orow[i] = z4;

    __syncthreads();

    // ---- scatter_add probs at tgt_index (atomic handles duplicates) ----
    if (tid < 32) {
        atomicAdd(out + (size_t)row * VV + sm_idx[tid], sm_prob[tid]);
    }
}

extern "C" void kernel_launch(void* const* d_in, const int* in_sizes, int n_in,
                              void* d_out, int out_size)
{
    // metadata order (setup_inputs order):
    // 0 tgt_index i32, 1 knn_dists f32, 2 knn_key_feature f32,
    // 3 network_probs f32 (UNUSED — dead code in reference),
    // 4 network_select_probs f32, 5 dfc_w (UNUSED), 6 dfc_b (UNUSED),
    // 7 fc1_w1, 8 fc1_b1, 9 fc1_w2, 10 fc1_b2,
    // 11 fc2_w1, 12 fc2_b1, 13 fc2_w2, 14 fc2_b2
    const int*   tgt  = (const int*)  d_in[0];
    const float* kd   = (const float*)d_in[1];
    const float* kkf  = (const float*)d_in[2];
    const float* nsp  = (const float*)d_in[4];
    const float* f1w1 = (const float*)d_in[7];
    const float* f1b1 = (const float*)d_in[8];
    const float* f1w2 = (const float*)d_in[9];
    const float* f1b2 = (const float*)d_in[10];
    const float* f2w1 = (const float*)d_in[11];
    const float* f2b1 = (const float*)d_in[12];
    const float* f2w2 = (const float*)d_in[13];
    const float* f2b2 = (const float*)d_in[14];
    float* out = (float*)d_out;

    robust_combiner_kernel<<<ROWS, THREADS>>>(
        tgt, kd, kkf, nsp,
        f1w1, f1b1, f1w2, f1b2,
        f2w1, f2b1, f2w2, f2b2,
        out);
}

// round 4
// speedup vs baseline: 1.0121x; 1.0121x over previous
#include <cuda_runtime.h>
#include <cuda_bf16.h>
#include <math.h>

// Problem constants
#define BB 4
#define SS 1024
#define KK 32
#define VV 32000
#define ROWS (BB * SS)        // 4096
#define THREADS 256
#define FULL 0xFFFFFFFFu

// Chunks of float4 per row
#define CHUNKS (VV / 4)       // 8000
#define ZTHREADS (THREADS - 32)  // 224 store threads (warps 1..7)

__global__ __launch_bounds__(THREADS)
void robust_combiner_kernel(
    const int*   __restrict__ tgt_index,            // [ROWS, 32]
    const float* __restrict__ knn_dists,            // [ROWS, 32]
    const float* __restrict__ knn_key_feature,      // [ROWS, 32]
    const float* __restrict__ network_select_probs, // [ROWS, 32]
    const float* __restrict__ fc1_w1,               // [2,4]
    const float* __restrict__ fc1_b1,               // [4]
    const float* __restrict__ fc1_w2,               // [4,1]
    const float* __restrict__ fc1_b2,               // [1]
    const float* __restrict__ fc2_w1,               // [64,32]
    const float* __restrict__ fc2_b1,               // [32]
    const float* __restrict__ fc2_w2,               // [32,2]
    const float* __restrict__ fc2_b2,               // [2]
    float*       __restrict__ out)                  // [ROWS, 32000]
{
    __shared__ float sm_prob[KK];
    __shared__ int   sm_idx[KK];

    const int row  = blockIdx.x;
    const int tid  = threadIdx.x;
    const int lane = tid & 31;

    float* __restrict__ orow = out + (size_t)row * VV;

    if (tid >= 32) {
        // ===== warps 1..7: stream zeros immediately (evict-first) =====
        float4* o4 = reinterpret_cast<float4*>(orow);
        const float4 z4 = make_float4(0.f, 0.f, 0.f, 0.f);
        #pragma unroll 4
        for (int i = tid - 32; i < CHUNKS; i += ZTHREADS)
            __stcs(&o4[i], z4);
    } else {
        // ===== warp 0: per-row math, fully overlapped with the zero stream =====
        const int base = row * KK + lane;
        const int   t  = tgt_index[base];
        const float d  = knn_dists[base];
        const float lkf = logf(knn_key_feature[base]);
        const float lsp = logf(network_select_probs[base]);

        // ---- label_counts: distinct nonzero labels in prefix [0..lane] ----
        int dup = 0;
        #pragma unroll
        for (int m = 0; m < KK; m++) {
            int tm = __shfl_sync(FULL, t, m);
            if (m < lane && tm == t) dup = 1;
        }
        int c = (t != 0 && !dup) ? 1 : 0;
        #pragma unroll
        for (int off = 1; off < 32; off <<= 1) {
            int v = __shfl_up_sync(FULL, c, off);
            if (lane >= off) c += v;
        }
        const float lc = (float)c;

        // ---- noise_logit: Linear(2,4) -> tanh -> Linear(4,1) ----
        float noise = fc1_b2[0];
        #pragma unroll
        for (int j = 0; j < 4; j++) {
            float h = tanhf(lkf * fc1_w1[j] + lsp * fc1_w1[4 + j] + fc1_b1[j]);
            noise += h * fc1_w2[j];
        }

        // ---- fc2: Linear(64,32)->tanh->Linear(32,2)[1]; lane = hidden unit ----
        // gather knn_dists / label_counts across the warp via shuffle
        float acc = fc2_b1[lane];
        #pragma unroll
        for (int m = 0; m < KK; m++) {
            float dm = __shfl_sync(FULL, d, m);
            acc = fmaf(dm, fc2_w1[m * 32 + lane], acc);
        }
        #pragma unroll
        for (int m = 0; m < KK; m++) {
            float lcm = __shfl_sync(FULL, lc, m);
            acc = fmaf(lcm, fc2_w1[(KK + m) * 32 + lane], acc);
        }
        float h = tanhf(acc);

        // lambda_logit[1] warp-reduce
        float part = h * fc2_w2[lane * 2 + 1];
        #pragma unroll
        for (int off = 16; off >= 1; off >>= 1)
            part += __shfl_xor_sync(FULL, part, off);
        const float tempe = 1.0f / (1.0f + expf(-(part + fc2_b2[1])));

        // ---- probs = softmax(-d * tempe + noise) over K ----
        float logit = fmaf(-d, tempe, noise);
        float mx = logit;
        #pragma unroll
        for (int off = 16; off >= 1; off >>= 1)
            mx = fmaxf(mx, __shfl_xor_sync(FULL, mx, off));
        float e = expf(logit - mx);
        float s = e;
        #pragma unroll
        for (int off = 16; off >= 1; off >>= 1)
            s += __shfl_xor_sync(FULL, s, off);

        sm_prob[lane] = e / s;
        sm_idx[lane]  = t;
    }

    __syncthreads();

    // ---- scatter_add probs at tgt_index (atomic handles duplicates) ----
    if (tid < 32) {
        atomicAdd(orow + sm_idx[tid], sm_prob[tid]);
    }
}

extern "C" void kernel_launch(void* const* d_in, const int* in_sizes, int n_in,
                              void* d_out, int out_size)
{
    // metadata order (setup_inputs order):
    // 0 tgt_index i32, 1 knn_dists f32, 2 knn_key_feature f32,
    // 3 network_probs f32 (UNUSED — dead code in reference),
    // 4 network_select_probs f32, 5 dfc_w (UNUSED), 6 dfc_b (UNUSED),
    // 7 fc1_w1, 8 fc1_b1, 9 fc1_w2, 10 fc1_b2,
    // 11 fc2_w1, 12 fc2_b1, 13 fc2_w2, 14 fc2_b2
    const int*   tgt  = (const int*)  d_in[0];
    const float* kd   = (const float*)d_in[1];
    const float* kkf  = (const float*)d_in[2];
    const float* nsp  = (const float*)d_in[4];
    const float* f1w1 = (const float*)d_in[7];
    const float* f1b1 = (const float*)d_in[8];
    const float* f1w2 = (const float*)d_in[9];
    const float* f1b2 = (const float*)d_in[10];
    const float* f2w1 = (const float*)d_in[11];
    const float* f2b1 = (const float*)d_in[12];
    const float* f2w2 = (const float*)d_in[13];
    const float* f2b2 = (const float*)d_in[14];
    float* out = (float*)d_out;

    robust_combiner_kernel<<<ROWS, THREADS>>>(
        tgt, kd, kkf, nsp,
        f1w1, f1b1, f1w2, f1b2,
        f2w1, f2b1, f2w2, f2b2,
        out);
}